// round 1
// baseline (speedup 1.0000x reference)
#include <cuda_runtime.h>
#include <math.h>

// Problem constants
#define Bc   4096
#define Dc   512
#define Hc   1024
#define Kc   8
#define Oc   256
#define NHc  4
#define HDc  256
#define H3c  3072
#define KH3c 24576   // K * 3H

// ---------------- scratch (static device globals; no runtime allocation) ----
__device__ float g_gi[(size_t)Bc * KH3c];      // (B, K*3H)
__device__ float g_gh[(size_t)Bc * KH3c];      // (B, K*3H)
__device__ float g_query[(size_t)Bc * Hc];     // (B, H)
__device__ float g_q[(size_t)Bc * Hc];         // (B, H)
__device__ float g_k[(size_t)Bc * Kc * Hc];    // (B*K, H)
__device__ float g_v[(size_t)Bc * Kc * Hc];    // (B*K, H)
__device__ float g_ctx[(size_t)Bc * Hc];       // (B, H)
__device__ float g_attno[(size_t)Bc * Hc];     // (B, H)
__device__ float g_context[(size_t)Bc * Hc];   // (B, H)
__device__ float g_mixed[(size_t)Bc * Hc];     // (B, H)

// ---------------------------------------------------------------------------
// Generic TN GEMM:  C[M,N] = A[M,Kd] * B[N,Kd]^T + bias[N]
// A row-major lda, B row-major ldb (reduction dim contiguous for both).
// blockIdx.z offsets pointers by (Az, Bz, Cz, biasz) for batched (per-expert).
// Tiles: 128x128x16, 256 threads, 8x8 per-thread microtile.
// All M,N must be multiples of 128; Kd multiple of 16. No bounds checks.
// ---------------------------------------------------------------------------
__global__ __launch_bounds__(256)
void gemm_tn(const float* __restrict__ A, int lda, long Az,
             const float* __restrict__ Bm, int ldb, long Bz,
             float* __restrict__ C, int ldc, long Cz,
             const float* __restrict__ bias, int biasz,
             int Kd)
{
    A    += (long)blockIdx.z * Az;
    Bm   += (long)blockIdx.z * Bz;
    C    += (long)blockIdx.z * Cz;
    bias += (long)blockIdx.z * biasz;

    __shared__ float As[16][128];
    __shared__ float Bs[16][128];

    const int tid = threadIdx.x;
    const int m0 = blockIdx.y * 128;
    const int n0 = blockIdx.x * 128;
    const int tm = tid >> 4;      // 0..15
    const int tn = tid & 15;      // 0..15

    float acc[8][8];
#pragma unroll
    for (int i = 0; i < 8; i++)
#pragma unroll
        for (int j = 0; j < 8; j++) acc[i][j] = 0.f;

    for (int k0 = 0; k0 < Kd; k0 += 16) {
        // cooperative load: 512 float4 per operand tile, 2 per thread
#pragma unroll
        for (int i = 0; i < 2; i++) {
            int idx = tid + i * 256;
            int rr = idx >> 2;            // 0..127 (tile row)
            int cc = (idx & 3) << 2;      // 0,4,8,12 (k within tile)
            float4 a = *(const float4*)(A + (size_t)(m0 + rr) * lda + k0 + cc);
            As[cc + 0][rr] = a.x; As[cc + 1][rr] = a.y;
            As[cc + 2][rr] = a.z; As[cc + 3][rr] = a.w;
            float4 b = *(const float4*)(Bm + (size_t)(n0 + rr) * ldb + k0 + cc);
            Bs[cc + 0][rr] = b.x; Bs[cc + 1][rr] = b.y;
            Bs[cc + 2][rr] = b.z; Bs[cc + 3][rr] = b.w;
        }
        __syncthreads();

#pragma unroll
        for (int kk = 0; kk < 16; kk++) {
            float ar[8], br[8];
            *(float4*)&ar[0] = *(const float4*)&As[kk][tm * 4];
            *(float4*)&ar[4] = *(const float4*)&As[kk][64 + tm * 4];
            *(float4*)&br[0] = *(const float4*)&Bs[kk][tn * 4];
            *(float4*)&br[4] = *(const float4*)&Bs[kk][64 + tn * 4];
#pragma unroll
            for (int i = 0; i < 8; i++)
#pragma unroll
                for (int j = 0; j < 8; j++)
                    acc[i][j] += ar[i] * br[j];
        }
        __syncthreads();
    }

    // epilogue with bias
#pragma unroll
    for (int ih = 0; ih < 2; ih++)
#pragma unroll
        for (int i = 0; i < 4; i++) {
            int row = m0 + ih * 64 + tm * 4 + i;
#pragma unroll
            for (int jh = 0; jh < 2; jh++) {
                int col = n0 + jh * 64 + tn * 4;
                float4 v;
                v.x = acc[ih * 4 + i][jh * 4 + 0] + bias[col + 0];
                v.y = acc[ih * 4 + i][jh * 4 + 1] + bias[col + 1];
                v.z = acc[ih * 4 + i][jh * 4 + 2] + bias[col + 2];
                v.w = acc[ih * 4 + i][jh * 4 + 3] + bias[col + 3];
                *(float4*)(C + (size_t)row * ldc + col) = v;
            }
        }
}

// ---------------------------------------------------------------------------
// GRU pointwise + per-expert LayerNorm. One block per (b,k) row (H=1024).
// ---------------------------------------------------------------------------
__global__ __launch_bounds__(256)
void gru_ln_kernel(const float* __restrict__ hp,
                   const float* __restrict__ lng, const float* __restrict__ lnb,
                   float* __restrict__ outh)
{
    int bk = blockIdx.x;              // b*K + k
    int b = bk >> 3, k = bk & 7;
    const float* gir = g_gi + (size_t)b * KH3c + k * H3c;
    const float* ghr = g_gh + (size_t)b * KH3c + k * H3c;
    const float* hpr = hp + (size_t)bk * Hc;
    int tid = threadIdx.x;

    float hv[4];
    float s = 0.f, sq = 0.f;
#pragma unroll
    for (int j = 0; j < 4; j++) {
        int h = tid + j * 256;
        float ir = gir[h], iz = gir[Hc + h], inn = gir[2 * Hc + h];
        float hr = ghr[h], hz = ghr[Hc + h], hn = ghr[2 * Hc + h];
        float r = 1.f / (1.f + expf(-(ir + hr)));
        float z = 1.f / (1.f + expf(-(iz + hz)));
        float n = tanhf(inn + r * hn);
        float v = (1.f - z) * n + z * hpr[h];
        hv[j] = v; s += v; sq += v * v;
    }
    __shared__ float sa[8], sb[8];
#pragma unroll
    for (int o = 16; o; o >>= 1) {
        s  += __shfl_xor_sync(0xffffffffu, s, o);
        sq += __shfl_xor_sync(0xffffffffu, sq, o);
    }
    if ((tid & 31) == 0) { sa[tid >> 5] = s; sb[tid >> 5] = sq; }
    __syncthreads();
    float ts = 0.f, tq = 0.f;
#pragma unroll
    for (int w = 0; w < 8; w++) { ts += sa[w]; tq += sb[w]; }
    float mean = ts * (1.f / (float)Hc);
    float var = tq * (1.f / (float)Hc) - mean * mean;
    float rstd = rsqrtf(var + 1e-5f);
#pragma unroll
    for (int j = 0; j < 4; j++) {
        int h = tid + j * 256;
        outh[(size_t)bk * Hc + h] = (hv[j] - mean) * rstd * lng[k * Hc + h] + lnb[k * Hc + h];
    }
}

// ---------------------------------------------------------------------------
// Attention over K=8 experts. One block per (b, head). HD=256, 256 threads.
// ---------------------------------------------------------------------------
__global__ __launch_bounds__(256)
void attn_kernel()
{
    int b = blockIdx.x / NHc;
    int n = blockIdx.x % NHc;
    const float* qv = g_q + (size_t)b * Hc + n * HDc;
    __shared__ float sc[Kc], at[Kc];
    int wid = threadIdx.x >> 5, lane = threadIdx.x & 31;

    // warp `wid` computes score for expert `wid`
    const float* kr = g_k + ((size_t)(b * Kc + wid)) * Hc + n * HDc;
    float s = 0.f;
#pragma unroll
    for (int d = lane; d < HDc; d += 32) s += qv[d] * kr[d];
#pragma unroll
    for (int o = 16; o; o >>= 1) s += __shfl_xor_sync(0xffffffffu, s, o);
    if (lane == 0) sc[wid] = s * (1.f / 16.f);   // 1/sqrt(HD)=1/16
    __syncthreads();
    if (threadIdx.x == 0) {
        float mx = sc[0];
#pragma unroll
        for (int k2 = 1; k2 < Kc; k2++) mx = fmaxf(mx, sc[k2]);
        float den = 0.f;
#pragma unroll
        for (int k2 = 0; k2 < Kc; k2++) { at[k2] = expf(sc[k2] - mx); den += at[k2]; }
        float inv = 1.f / den;
#pragma unroll
        for (int k2 = 0; k2 < Kc; k2++) at[k2] *= inv;
    }
    __syncthreads();
    int d = threadIdx.x;   // HD == blockDim == 256
    float c = 0.f;
#pragma unroll
    for (int k2 = 0; k2 < Kc; k2++)
        c += at[k2] * g_v[((size_t)(b * Kc + k2)) * Hc + n * HDc + d];
    g_ctx[(size_t)b * Hc + n * HDc + d] = c;
}

// ---------------------------------------------------------------------------
// context = LayerNorm(query + attn_out). One block per b.
// ---------------------------------------------------------------------------
__global__ __launch_bounds__(256)
void ln_res_kernel(const float* __restrict__ g, const float* __restrict__ bb)
{
    int b = blockIdx.x;
    const float* qr = g_query + (size_t)b * Hc;
    const float* ar = g_attno + (size_t)b * Hc;
    int tid = threadIdx.x;
    float hv[4]; float s = 0.f, sq = 0.f;
#pragma unroll
    for (int j = 0; j < 4; j++) {
        int h = tid + j * 256;
        float v = qr[h] + ar[h];
        hv[j] = v; s += v; sq += v * v;
    }
    __shared__ float sa[8], sb[8];
#pragma unroll
    for (int o = 16; o; o >>= 1) {
        s  += __shfl_xor_sync(0xffffffffu, s, o);
        sq += __shfl_xor_sync(0xffffffffu, sq, o);
    }
    if ((tid & 31) == 0) { sa[tid >> 5] = s; sb[tid >> 5] = sq; }
    __syncthreads();
    float ts = 0.f, tq = 0.f;
#pragma unroll
    for (int w = 0; w < 8; w++) { ts += sa[w]; tq += sb[w]; }
    float mean = ts * (1.f / (float)Hc);
    float var = tq * (1.f / (float)Hc) - mean * mean;
    float rstd = rsqrtf(var + 1e-5f);
#pragma unroll
    for (int j = 0; j < 4; j++) {
        int h = tid + j * 256;
        g_context[(size_t)b * Hc + h] = (hv[j] - mean) * rstd * g[h] + bb[h];
    }
}

// ---------------------------------------------------------------------------
// Gate logits + softmax + expert mixing. One block per b.
// Writes logits, g_t to output; mixed_h to scratch.
// ---------------------------------------------------------------------------
__global__ __launch_bounds__(256)
void gate_kernel(const float* __restrict__ Wg, const float* __restrict__ bg,
                 const float* __restrict__ h_new,
                 float* __restrict__ out_g, float* __restrict__ out_l)
{
    int b = blockIdx.x;
    int tid = threadIdx.x;
    int wid = tid >> 5, lane = tid & 31;
    __shared__ float lg[Kc], gt[Kc];

    const float* cr = g_context + (size_t)b * Hc;
    float s = 0.f;
#pragma unroll
    for (int h = lane; h < Hc; h += 32) s += cr[h] * Wg[wid * Hc + h];
#pragma unroll
    for (int o = 16; o; o >>= 1) s += __shfl_xor_sync(0xffffffffu, s, o);
    if (lane == 0) lg[wid] = s + bg[wid];
    __syncthreads();
    if (tid == 0) {
        float mx = lg[0];
#pragma unroll
        for (int k2 = 1; k2 < Kc; k2++) mx = fmaxf(mx, lg[k2]);
        float den = 0.f;
#pragma unroll
        for (int k2 = 0; k2 < Kc; k2++) { gt[k2] = expf(lg[k2] - mx); den += gt[k2]; }
        float inv = 1.f / den;
#pragma unroll
        for (int k2 = 0; k2 < Kc; k2++) gt[k2] *= inv;
    }
    __syncthreads();
#pragma unroll
    for (int j = 0; j < 4; j++) {
        int h = tid + j * 256;
        float m = 0.f;
#pragma unroll
        for (int k2 = 0; k2 < Kc; k2++)
            m += gt[k2] * h_new[((size_t)(b * Kc + k2)) * Hc + h];
        g_mixed[(size_t)b * Hc + h] = m;
    }
    if (tid < Kc) { out_l[b * Kc + tid] = lg[tid]; out_g[b * Kc + tid] = gt[tid]; }
}

// ---------------------------------------------------------------------------
extern "C" void kernel_launch(void* const* d_in, const int* in_sizes, int n_in,
                              void* d_out, int out_size)
{
    const float* x_t    = (const float*)d_in[0];
    const float* h_prev = (const float*)d_in[1];
    const float* W_ih   = (const float*)d_in[2];
    const float* W_hh   = (const float*)d_in[3];
    const float* b_ih   = (const float*)d_in[4];
    const float* b_hh   = (const float*)d_in[5];
    const float* ln_g   = (const float*)d_in[6];
    const float* ln_b   = (const float*)d_in[7];
    const float* Wqp    = (const float*)d_in[8];
    const float* bqp    = (const float*)d_in[9];
    const float* W_q    = (const float*)d_in[10];
    const float* W_k    = (const float*)d_in[11];
    const float* W_v    = (const float*)d_in[12];
    const float* b_q    = (const float*)d_in[13];
    const float* b_k    = (const float*)d_in[14];
    const float* b_v    = (const float*)d_in[15];
    const float* W_o    = (const float*)d_in[16];
    const float* b_o    = (const float*)d_in[17];
    const float* aln_g  = (const float*)d_in[18];
    const float* aln_b  = (const float*)d_in[19];
    const float* W_gate = (const float*)d_in[20];
    const float* b_gate = (const float*)d_in[21];
    const float* W_read = (const float*)d_in[22];
    const float* b_read = (const float*)d_in[23];

    float* out   = (float*)d_out;
    float* out_h = out;                                  // (B,K,H)
    float* out_y = out_h + (size_t)Bc * Kc * Hc;         // (B,O)
    float* out_g = out_y + (size_t)Bc * Oc;              // (B,K)
    float* out_l = out_g + (size_t)Bc * Kc;              // (B,K)

    float *pgi, *pgh, *pquery, *pq, *pk, *pv, *pctx, *pattno, *pmixed;
    cudaGetSymbolAddress((void**)&pgi,    g_gi);
    cudaGetSymbolAddress((void**)&pgh,    g_gh);
    cudaGetSymbolAddress((void**)&pquery, g_query);
    cudaGetSymbolAddress((void**)&pq,     g_q);
    cudaGetSymbolAddress((void**)&pk,     g_k);
    cudaGetSymbolAddress((void**)&pv,     g_v);
    cudaGetSymbolAddress((void**)&pctx,   g_ctx);
    cudaGetSymbolAddress((void**)&pattno, g_attno);
    cudaGetSymbolAddress((void**)&pmixed, g_mixed);

    dim3 blk(256);

    // gi = x_t @ W_ih^T + b_ih        (4096 x 24576, Kd=512)
    gemm_tn<<<dim3(KH3c / 128, Bc / 128, 1), blk>>>(
        x_t, Dc, 0, W_ih, Dc, 0, pgi, KH3c, 0, b_ih, 0, Dc);

    // gh[k] = h_prev[:,k,:] @ W_hh[k]^T + b_hh[k]   (per-expert, z=8)
    gemm_tn<<<dim3(H3c / 128, Bc / 128, Kc), blk>>>(
        h_prev, Kc * Hc, (long)Hc,
        W_hh, Hc, (long)H3c * Hc,
        pgh, KH3c, (long)H3c,
        b_hh, H3c, Hc);

    // query = x_t @ Wq_proj^T + bq    (4096 x 1024, Kd=512)
    gemm_tn<<<dim3(Hc / 128, Bc / 128, 1), blk>>>(
        x_t, Dc, 0, Wqp, Dc, 0, pquery, Hc, 0, bqp, 0, Dc);

    // GRU pointwise + per-expert LN -> h_new (written to output)
    gru_ln_kernel<<<Bc * Kc, blk>>>(h_prev, ln_g, ln_b, out_h);

    // q = query @ W_q^T + b_q
    gemm_tn<<<dim3(Hc / 128, Bc / 128, 1), blk>>>(
        pquery, Hc, 0, W_q, Hc, 0, pq, Hc, 0, b_q, 0, Hc);

    // k = h_new @ W_k^T + b_k   (32768 x 1024)
    gemm_tn<<<dim3(Hc / 128, (Bc * Kc) / 128, 1), blk>>>(
        out_h, Hc, 0, W_k, Hc, 0, pk, Hc, 0, b_k, 0, Hc);

    // v = h_new @ W_v^T + b_v
    gemm_tn<<<dim3(Hc / 128, (Bc * Kc) / 128, 1), blk>>>(
        out_h, Hc, 0, W_v, Hc, 0, pv, Hc, 0, b_v, 0, Hc);

    // attention over experts -> ctx
    attn_kernel<<<Bc * NHc, blk>>>();

    // attn_out = ctx @ W_o^T + b_o
    gemm_tn<<<dim3(Hc / 128, Bc / 128, 1), blk>>>(
        pctx, Hc, 0, W_o, Hc, 0, pattno, Hc, 0, b_o, 0, Hc);

    // context = LN(query + attn_out)
    ln_res_kernel<<<Bc, blk>>>(aln_g, aln_b);

    // logits/g_t/mixed_h
    gate_kernel<<<Bc, blk>>>(W_gate, b_gate, out_h, out_g, out_l);

    // y_hat = mixed_h @ W_read^T + b_read   (4096 x 256)
    gemm_tn<<<dim3(Oc / 128, Bc / 128, 1), blk>>>(
        pmixed, Hc, 0, W_read, Hc, 0, out_y, Oc, 0, b_read, 0, Hc);
}

// round 3
// speedup vs baseline: 3.0422x; 3.0422x over previous
#include <cuda_runtime.h>
#include <math.h>
#include <stdint.h>

// Problem constants
#define Bc   4096
#define Dc   512
#define Hc   1024
#define Kc   8
#define Oc   256
#define NHc  4
#define HDc  256
#define H3c  3072
#define KH3c 24576   // K * 3H

// ---------------- scratch (static device globals; no runtime allocation) ----
__device__ float g_gi[(size_t)Bc * KH3c];      // (B, K*3H)
__device__ float g_gh[(size_t)Bc * KH3c];      // (B, K*3H)
__device__ float g_query[(size_t)Bc * Hc];     // (B, H)
__device__ float g_q[(size_t)Bc * Hc];         // (B, H)
__device__ float g_k[(size_t)Bc * Kc * Hc];    // (B*K, H)
__device__ float g_v[(size_t)Bc * Kc * Hc];    // (B*K, H)
__device__ float g_ctx[(size_t)Bc * Hc];       // (B, H)
__device__ float g_attno[(size_t)Bc * Hc];     // (B, H)
__device__ float g_context[(size_t)Bc * Hc];   // (B, H)
__device__ float g_mixed[(size_t)Bc * Hc];     // (B, H)

// ---------------------------------------------------------------------------
// helpers
// ---------------------------------------------------------------------------
__device__ __forceinline__ uint32_t smem_u32(const void* p) {
    return (uint32_t)__cvta_generic_to_shared(p);
}
__device__ __forceinline__ float to_tf32(float x) {
    float r; asm("cvt.rna.tf32.f32 %0, %1;" : "=f"(r) : "f"(x)); return r;
}
__device__ __forceinline__ void ldsm4(uint32_t addr, uint32_t& r0, uint32_t& r1,
                                      uint32_t& r2, uint32_t& r3) {
    asm volatile("ldmatrix.sync.aligned.m8n8.x4.shared.b16 {%0,%1,%2,%3}, [%4];"
                 : "=r"(r0), "=r"(r1), "=r"(r2), "=r"(r3) : "r"(addr));
}
__device__ __forceinline__ void mma_tf32(float* d, const uint32_t* a, const uint32_t* b) {
    asm volatile(
        "mma.sync.aligned.m16n8k8.row.col.f32.tf32.tf32.f32 "
        "{%0,%1,%2,%3}, {%4,%5,%6,%7}, {%8,%9}, {%0,%1,%2,%3};"
        : "+f"(d[0]), "+f"(d[1]), "+f"(d[2]), "+f"(d[3])
        : "r"(a[0]), "r"(a[1]), "r"(a[2]), "r"(a[3]), "r"(b[0]), "r"(b[1]));
}

// ---------------------------------------------------------------------------
// TF32 tensor-core TN GEMM: C[M,N] = A[M,Kd] * B[N,Kd]^T + bias[N]
// Reduction dim contiguous for A and B. blockIdx.z batching via (Az,Bz,Cz,biasz).
// Tile: 128x128 x BK=16. 8 warps, each 32(m) x 64(n). smem double-buffered,
// XOR swizzle (chunk ^ ((row>>1)&3)) -> conflict-free STS.128 and ldmatrix.
// M,N multiples of 128; Kd multiple of 16.
// ---------------------------------------------------------------------------
__global__ __launch_bounds__(256, 2)
void gemm_tf32(const float* __restrict__ A, int lda, long long Az,
               const float* __restrict__ Bm, int ldb, long long Bz,
               float* __restrict__ C, int ldcc, long long Cz,
               const float* __restrict__ bias, int biasz,
               int Kd)
{
    A    += (long long)blockIdx.z * Az;
    Bm   += (long long)blockIdx.z * Bz;
    C    += (long long)blockIdx.z * Cz;
    bias += (long long)blockIdx.z * biasz;

    __shared__ float As[2][128 * 16];
    __shared__ float Bs[2][128 * 16];

    const int tid  = threadIdx.x;
    const int lane = tid & 31;
    const int w    = tid >> 5;
    const int wm   = (w & 3) * 32;     // warp m offset in tile
    const int wn   = (w >> 2) * 64;    // warp n offset in tile
    const int m0   = blockIdx.y * 128;
    const int n0   = blockIdx.x * 128;

    // global->smem staging mapping: idx = tid + i*256 covers 512 float4
    const int ldrow = tid >> 2;        // 0..63  (+64 for i=1)
    const int ldc4  = tid & 3;         // 16B chunk within row

    // ldmatrix source lane mappings
    const int a_row0  = wm + (lane & 15);             // rows 0..15 of mtile
    const int a_khalf = lane >> 4;                    // chunk half
    const int b_row0  = wn + ((lane >> 4) & 1) * 8 + (lane & 7);
    const int b_half  = (lane >> 3) & 1;

    float acc[2][8][4];
#pragma unroll
    for (int mt = 0; mt < 2; mt++)
#pragma unroll
        for (int nt = 0; nt < 8; nt++)
#pragma unroll
            for (int i = 0; i < 4; i++) acc[mt][nt][i] = 0.f;

    float4 stA[2], stB[2];

    // prologue: load + convert + store k-tile 0 into stage 0
#pragma unroll
    for (int i = 0; i < 2; i++) {
        int row = ldrow + i * 64;
        stA[i] = *(const float4*)(A + (size_t)(m0 + row) * lda + ldc4 * 4);
        stB[i] = *(const float4*)(Bm + (size_t)(n0 + row) * ldb + ldc4 * 4);
    }
#pragma unroll
    for (int i = 0; i < 2; i++) {
        int row = ldrow + i * 64;
        int off = row * 16 + ((ldc4 ^ ((row >> 1) & 3)) << 2);
        float* pa = &As[0][off];
        pa[0] = to_tf32(stA[i].x); pa[1] = to_tf32(stA[i].y);
        pa[2] = to_tf32(stA[i].z); pa[3] = to_tf32(stA[i].w);
        float* pb = &Bs[0][off];
        pb[0] = to_tf32(stB[i].x); pb[1] = to_tf32(stB[i].y);
        pb[2] = to_tf32(stB[i].z); pb[3] = to_tf32(stB[i].w);
    }
    __syncthreads();

    const int nk = Kd >> 4;
    for (int kt = 0; kt < nk; kt++) {
        const int st = kt & 1;
        if (kt + 1 < nk) {
            int koff = (kt + 1) * 16;
#pragma unroll
            for (int i = 0; i < 2; i++) {
                int row = ldrow + i * 64;
                stA[i] = *(const float4*)(A + (size_t)(m0 + row) * lda + koff + ldc4 * 4);
                stB[i] = *(const float4*)(Bm + (size_t)(n0 + row) * ldb + koff + ldc4 * 4);
            }
        }
        // compute on stage st
#pragma unroll
        for (int ks = 0; ks < 2; ks++) {
            uint32_t af[2][4], bf[4][4];
#pragma unroll
            for (int mt = 0; mt < 2; mt++) {
                int r = a_row0 + mt * 16;
                int chunk = ks * 2 + a_khalf;
                uint32_t addr = smem_u32(&As[st][r * 16 + ((chunk ^ ((r >> 1) & 3)) << 2)]);
                ldsm4(addr, af[mt][0], af[mt][1], af[mt][2], af[mt][3]);
            }
#pragma unroll
            for (int jp = 0; jp < 4; jp++) {
                int r = b_row0 + jp * 16;
                int chunk = ks * 2 + b_half;
                uint32_t addr = smem_u32(&Bs[st][r * 16 + ((chunk ^ ((r >> 1) & 3)) << 2)]);
                ldsm4(addr, bf[jp][0], bf[jp][1], bf[jp][2], bf[jp][3]);
            }
#pragma unroll
            for (int mt = 0; mt < 2; mt++)
#pragma unroll
                for (int jp = 0; jp < 4; jp++) {
                    mma_tf32(acc[mt][jp * 2 + 0], af[mt], &bf[jp][0]);
                    mma_tf32(acc[mt][jp * 2 + 1], af[mt], &bf[jp][2]);
                }
        }
        // stage next tile
        if (kt + 1 < nk) {
            const int st2 = st ^ 1;
#pragma unroll
            for (int i = 0; i < 2; i++) {
                int row = ldrow + i * 64;
                int off = row * 16 + ((ldc4 ^ ((row >> 1) & 3)) << 2);
                float* pa = &As[st2][off];
                pa[0] = to_tf32(stA[i].x); pa[1] = to_tf32(stA[i].y);
                pa[2] = to_tf32(stA[i].z); pa[3] = to_tf32(stA[i].w);
                float* pb = &Bs[st2][off];
                pb[0] = to_tf32(stB[i].x); pb[1] = to_tf32(stB[i].y);
                pb[2] = to_tf32(stB[i].z); pb[3] = to_tf32(stB[i].w);
            }
        }
        __syncthreads();
    }

    // epilogue: fragment layout c0,c1=(row, 2c),(row,2c+1); c2,c3=row+8
    const int crow = lane >> 2;
    const int ccol = (lane & 3) * 2;
#pragma unroll
    for (int mt = 0; mt < 2; mt++) {
        int r0 = m0 + wm + mt * 16 + crow;
#pragma unroll
        for (int nt = 0; nt < 8; nt++) {
            int col = n0 + wn + nt * 8 + ccol;
            float bx = bias[col], by = bias[col + 1];
            float2 v0 = make_float2(acc[mt][nt][0] + bx, acc[mt][nt][1] + by);
            float2 v1 = make_float2(acc[mt][nt][2] + bx, acc[mt][nt][3] + by);
            *(float2*)(C + (size_t)r0 * ldcc + col) = v0;
            *(float2*)(C + (size_t)(r0 + 8) * ldcc + col) = v1;
        }
    }
}

// ---------------------------------------------------------------------------
// GRU pointwise + per-expert LayerNorm. One block per (b,k) row (H=1024).
// ---------------------------------------------------------------------------
__global__ __launch_bounds__(256)
void gru_ln_kernel(const float* __restrict__ hp,
                   const float* __restrict__ lng, const float* __restrict__ lnb,
                   float* __restrict__ outh)
{
    int bk = blockIdx.x;
    int b = bk >> 3, k = bk & 7;
    const float* gir = g_gi + (size_t)b * KH3c + k * H3c;
    const float* ghr = g_gh + (size_t)b * KH3c + k * H3c;
    const float* hpr = hp + (size_t)bk * Hc;
    int tid = threadIdx.x;

    float hv[4];
    float s = 0.f, sq = 0.f;
#pragma unroll
    for (int j = 0; j < 4; j++) {
        int h = tid + j * 256;
        float ir = gir[h], iz = gir[Hc + h], inn = gir[2 * Hc + h];
        float hr = ghr[h], hz = ghr[Hc + h], hn = ghr[2 * Hc + h];
        float r = 1.f / (1.f + expf(-(ir + hr)));
        float z = 1.f / (1.f + expf(-(iz + hz)));
        float n = tanhf(inn + r * hn);
        float v = (1.f - z) * n + z * hpr[h];
        hv[j] = v; s += v; sq += v * v;
    }
    __shared__ float sa[8], sb[8];
#pragma unroll
    for (int o = 16; o; o >>= 1) {
        s  += __shfl_xor_sync(0xffffffffu, s, o);
        sq += __shfl_xor_sync(0xffffffffu, sq, o);
    }
    if ((tid & 31) == 0) { sa[tid >> 5] = s; sb[tid >> 5] = sq; }
    __syncthreads();
    float ts = 0.f, tq = 0.f;
#pragma unroll
    for (int ww = 0; ww < 8; ww++) { ts += sa[ww]; tq += sb[ww]; }
    float mean = ts * (1.f / (float)Hc);
    float var = tq * (1.f / (float)Hc) - mean * mean;
    float rstd = rsqrtf(var + 1e-5f);
#pragma unroll
    for (int j = 0; j < 4; j++) {
        int h = tid + j * 256;
        outh[(size_t)bk * Hc + h] = (hv[j] - mean) * rstd * lng[k * Hc + h] + lnb[k * Hc + h];
    }
}

// ---------------------------------------------------------------------------
// Attention over K=8 experts. One block per (b, head). HD=256, 256 threads.
// ---------------------------------------------------------------------------
__global__ __launch_bounds__(256)
void attn_kernel()
{
    int b = blockIdx.x / NHc;
    int n = blockIdx.x % NHc;
    const float* qv = g_q + (size_t)b * Hc + n * HDc;
    __shared__ float sc[Kc], at[Kc];
    int wid = threadIdx.x >> 5, lane = threadIdx.x & 31;

    const float* kr = g_k + ((size_t)(b * Kc + wid)) * Hc + n * HDc;
    float s = 0.f;
#pragma unroll
    for (int d = lane; d < HDc; d += 32) s += qv[d] * kr[d];
#pragma unroll
    for (int o = 16; o; o >>= 1) s += __shfl_xor_sync(0xffffffffu, s, o);
    if (lane == 0) sc[wid] = s * (1.f / 16.f);
    __syncthreads();
    if (threadIdx.x == 0) {
        float mx = sc[0];
#pragma unroll
        for (int k2 = 1; k2 < Kc; k2++) mx = fmaxf(mx, sc[k2]);
        float den = 0.f;
#pragma unroll
        for (int k2 = 0; k2 < Kc; k2++) { at[k2] = expf(sc[k2] - mx); den += at[k2]; }
        float inv = 1.f / den;
#pragma unroll
        for (int k2 = 0; k2 < Kc; k2++) at[k2] *= inv;
    }
    __syncthreads();
    int d = threadIdx.x;
    float c = 0.f;
#pragma unroll
    for (int k2 = 0; k2 < Kc; k2++)
        c += at[k2] * g_v[((size_t)(b * Kc + k2)) * Hc + n * HDc + d];
    g_ctx[(size_t)b * Hc + n * HDc + d] = c;
}

// ---------------------------------------------------------------------------
// context = LayerNorm(query + attn_out). One block per b.
// ---------------------------------------------------------------------------
__global__ __launch_bounds__(256)
void ln_res_kernel(const float* __restrict__ g, const float* __restrict__ bb)
{
    int b = blockIdx.x;
    const float* qr = g_query + (size_t)b * Hc;
    const float* ar = g_attno + (size_t)b * Hc;
    int tid = threadIdx.x;
    float hv[4]; float s = 0.f, sq = 0.f;
#pragma unroll
    for (int j = 0; j < 4; j++) {
        int h = tid + j * 256;
        float v = qr[h] + ar[h];
        hv[j] = v; s += v; sq += v * v;
    }
    __shared__ float sa[8], sb[8];
#pragma unroll
    for (int o = 16; o; o >>= 1) {
        s  += __shfl_xor_sync(0xffffffffu, s, o);
        sq += __shfl_xor_sync(0xffffffffu, sq, o);
    }
    if ((tid & 31) == 0) { sa[tid >> 5] = s; sb[tid >> 5] = sq; }
    __syncthreads();
    float ts = 0.f, tq = 0.f;
#pragma unroll
    for (int ww = 0; ww < 8; ww++) { ts += sa[ww]; tq += sb[ww]; }
    float mean = ts * (1.f / (float)Hc);
    float var = tq * (1.f / (float)Hc) - mean * mean;
    float rstd = rsqrtf(var + 1e-5f);
#pragma unroll
    for (int j = 0; j < 4; j++) {
        int h = tid + j * 256;
        g_context[(size_t)b * Hc + h] = (hv[j] - mean) * rstd * g[h] + bb[h];
    }
}

// ---------------------------------------------------------------------------
// Gate logits + softmax + expert mixing. One block per b.
// ---------------------------------------------------------------------------
__global__ __launch_bounds__(256)
void gate_kernel(const float* __restrict__ Wg, const float* __restrict__ bg,
                 const float* __restrict__ h_new,
                 float* __restrict__ out_g, float* __restrict__ out_l)
{
    int b = blockIdx.x;
    int tid = threadIdx.x;
    int wid = tid >> 5, lane = tid & 31;
    __shared__ float lg[Kc], gt[Kc];

    const float* cr = g_context + (size_t)b * Hc;
    float s = 0.f;
#pragma unroll
    for (int h = lane; h < Hc; h += 32) s += cr[h] * Wg[wid * Hc + h];
#pragma unroll
    for (int o = 16; o; o >>= 1) s += __shfl_xor_sync(0xffffffffu, s, o);
    if (lane == 0) lg[wid] = s + bg[wid];
    __syncthreads();
    if (tid == 0) {
        float mx = lg[0];
#pragma unroll
        for (int k2 = 1; k2 < Kc; k2++) mx = fmaxf(mx, lg[k2]);
        float den = 0.f;
#pragma unroll
        for (int k2 = 0; k2 < Kc; k2++) { gt[k2] = expf(lg[k2] - mx); den += gt[k2]; }
        float inv = 1.f / den;
#pragma unroll
        for (int k2 = 0; k2 < Kc; k2++) gt[k2] *= inv;
    }
    __syncthreads();
#pragma unroll
    for (int j = 0; j < 4; j++) {
        int h = tid + j * 256;
        float m = 0.f;
#pragma unroll
        for (int k2 = 0; k2 < Kc; k2++)
            m += gt[k2] * h_new[((size_t)(b * Kc + k2)) * Hc + h];
        g_mixed[(size_t)b * Hc + h] = m;
    }
    if (tid < Kc) { out_l[b * Kc + tid] = lg[tid]; out_g[b * Kc + tid] = gt[tid]; }
}

// ---------------------------------------------------------------------------
extern "C" void kernel_launch(void* const* d_in, const int* in_sizes, int n_in,
                              void* d_out, int out_size)
{
    const float* x_t    = (const float*)d_in[0];
    const float* h_prev = (const float*)d_in[1];
    const float* W_ih   = (const float*)d_in[2];
    const float* W_hh   = (const float*)d_in[3];
    const float* b_ih   = (const float*)d_in[4];
    const float* b_hh   = (const float*)d_in[5];
    const float* ln_g   = (const float*)d_in[6];
    const float* ln_b   = (const float*)d_in[7];
    const float* Wqp    = (const float*)d_in[8];
    const float* bqp    = (const float*)d_in[9];
    const float* W_q    = (const float*)d_in[10];
    const float* W_k    = (const float*)d_in[11];
    const float* W_v    = (const float*)d_in[12];
    const float* b_q    = (const float*)d_in[13];
    const float* b_k    = (const float*)d_in[14];
    const float* b_v    = (const float*)d_in[15];
    const float* W_o    = (const float*)d_in[16];
    const float* b_o    = (const float*)d_in[17];
    const float* aln_g  = (const float*)d_in[18];
    const float* aln_b  = (const float*)d_in[19];
    const float* W_gate = (const float*)d_in[20];
    const float* b_gate = (const float*)d_in[21];
    const float* W_read = (const float*)d_in[22];
    const float* b_read = (const float*)d_in[23];

    float* out   = (float*)d_out;
    float* out_h = out;                                  // (B,K,H)
    float* out_y = out_h + (size_t)Bc * Kc * Hc;         // (B,O)
    float* out_g = out_y + (size_t)Bc * Oc;              // (B,K)
    float* out_l = out_g + (size_t)Bc * Kc;              // (B,K)

    float *pgi, *pgh, *pquery, *pq, *pk, *pv, *pctx, *pattno, *pmixed;
    cudaGetSymbolAddress((void**)&pgi,    g_gi);
    cudaGetSymbolAddress((void**)&pgh,    g_gh);
    cudaGetSymbolAddress((void**)&pquery, g_query);
    cudaGetSymbolAddress((void**)&pq,     g_q);
    cudaGetSymbolAddress((void**)&pk,     g_k);
    cudaGetSymbolAddress((void**)&pv,     g_v);
    cudaGetSymbolAddress((void**)&pctx,   g_ctx);
    cudaGetSymbolAddress((void**)&pattno, g_attno);
    cudaGetSymbolAddress((void**)&pmixed, g_mixed);

    dim3 blk(256);

    // gi = x_t @ W_ih^T + b_ih        (4096 x 24576, Kd=512)
    gemm_tf32<<<dim3(KH3c / 128, Bc / 128, 1), blk>>>(
        x_t, Dc, 0, W_ih, Dc, 0, pgi, KH3c, 0, b_ih, 0, Dc);

    // gh[k] = h_prev[:,k,:] @ W_hh[k]^T + b_hh[k]   (per-expert, z=8)
    gemm_tf32<<<dim3(H3c / 128, Bc / 128, Kc), blk>>>(
        h_prev, Kc * Hc, (long long)Hc,
        W_hh, Hc, (long long)H3c * Hc,
        pgh, KH3c, (long long)H3c,
        b_hh, H3c, Hc);

    // query = x_t @ Wq_proj^T + bq    (4096 x 1024, Kd=512)
    gemm_tf32<<<dim3(Hc / 128, Bc / 128, 1), blk>>>(
        x_t, Dc, 0, Wqp, Dc, 0, pquery, Hc, 0, bqp, 0, Dc);

    // GRU pointwise + per-expert LN -> h_new (written to output)
    gru_ln_kernel<<<Bc * Kc, blk>>>(h_prev, ln_g, ln_b, out_h);

    // q = query @ W_q^T + b_q
    gemm_tf32<<<dim3(Hc / 128, Bc / 128, 1), blk>>>(
        pquery, Hc, 0, W_q, Hc, 0, pq, Hc, 0, b_q, 0, Hc);

    // k = h_new @ W_k^T + b_k   (32768 x 1024)
    gemm_tf32<<<dim3(Hc / 128, (Bc * Kc) / 128, 1), blk>>>(
        out_h, Hc, 0, W_k, Hc, 0, pk, Hc, 0, b_k, 0, Hc);

    // v = h_new @ W_v^T + b_v
    gemm_tf32<<<dim3(Hc / 128, (Bc * Kc) / 128, 1), blk>>>(
        out_h, Hc, 0, W_v, Hc, 0, pv, Hc, 0, b_v, 0, Hc);

    // attention over experts -> ctx
    attn_kernel<<<Bc * NHc, blk>>>();

    // attn_out = ctx @ W_o^T + b_o
    gemm_tf32<<<dim3(Hc / 128, Bc / 128, 1), blk>>>(
        pctx, Hc, 0, W_o, Hc, 0, pattno, Hc, 0, b_o, 0, Hc);

    // context = LN(query + attn_out)
    ln_res_kernel<<<Bc, blk>>>(aln_g, aln_b);

    // logits/g_t/mixed_h
    gate_kernel<<<Bc, blk>>>(W_gate, b_gate, out_h, out_g, out_l);

    // y_hat = mixed_h @ W_read^T + b_read   (4096 x 256)
    gemm_tf32<<<dim3(Oc / 128, Bc / 128, 1), blk>>>(
        pmixed, Hc, 0, W_read, Hc, 0, out_y, Oc, 0, b_read, 0, Hc);
}

// round 4
// speedup vs baseline: 3.7978x; 1.2484x over previous
#include <cuda_runtime.h>
#include <math.h>
#include <stdint.h>

// Problem constants
#define Bc   4096
#define Dc   512
#define Hc   1024
#define Kc   8
#define Oc   256
#define NHc  4
#define HDc  256
#define H3c  3072
#define KH3c 24576   // K * 3H

// ---------------- scratch (static device globals; no runtime allocation) ----
__device__ float g_gi[(size_t)Bc * KH3c];
__device__ float g_gh[(size_t)Bc * KH3c];
__device__ float g_query[(size_t)Bc * Hc];
__device__ float g_query_rt[(size_t)Bc * Hc];
__device__ float g_q[(size_t)Bc * Hc];
__device__ float g_k[(size_t)Bc * Kc * Hc];
__device__ float g_v[(size_t)Bc * Kc * Hc];
__device__ float g_ctx[(size_t)Bc * Hc];
__device__ float g_attno[(size_t)Bc * Hc];
__device__ float g_context[(size_t)Bc * Hc];
__device__ float g_mixed[(size_t)Bc * Hc];
__device__ float g_hnew_rt[(size_t)Bc * Kc * Hc];
// tf32-rounded copies of inputs
__device__ float g_x_rt[(size_t)Bc * Dc];
__device__ float g_hprev_rt[(size_t)Bc * Kc * Hc];
__device__ float g_Wih_rt[(size_t)KH3c * Dc];
__device__ float g_Whh_rt[(size_t)Kc * H3c * Hc];
__device__ float g_Wqp_rt[(size_t)Hc * Dc];
__device__ float g_Wq_rt[(size_t)Hc * Hc];
__device__ float g_Wk_rt[(size_t)Hc * Hc];
__device__ float g_Wv_rt[(size_t)Hc * Hc];
__device__ float g_Wo_rt[(size_t)Hc * Hc];
__device__ float g_Wread_rt[(size_t)Oc * Hc];

// ---------------------------------------------------------------------------
// helpers
// ---------------------------------------------------------------------------
__device__ __forceinline__ uint32_t smem_u32(const void* p) {
    return (uint32_t)__cvta_generic_to_shared(p);
}
__device__ __forceinline__ float to_tf32(float x) {
    float r; asm("cvt.rna.tf32.f32 %0, %1;" : "=f"(r) : "f"(x)); return r;
}
__device__ __forceinline__ void ldsm4(uint32_t addr, uint32_t& r0, uint32_t& r1,
                                      uint32_t& r2, uint32_t& r3) {
    asm volatile("ldmatrix.sync.aligned.m8n8.x4.shared.b16 {%0,%1,%2,%3}, [%4];"
                 : "=r"(r0), "=r"(r1), "=r"(r2), "=r"(r3) : "r"(addr));
}
__device__ __forceinline__ void mma_tf32(float* d, const uint32_t* a, const uint32_t* b) {
    asm volatile(
        "mma.sync.aligned.m16n8k8.row.col.f32.tf32.tf32.f32 "
        "{%0,%1,%2,%3}, {%4,%5,%6,%7}, {%8,%9}, {%0,%1,%2,%3};"
        : "+f"(d[0]), "+f"(d[1]), "+f"(d[2]), "+f"(d[3])
        : "r"(a[0]), "r"(a[1]), "r"(a[2]), "r"(a[3]), "r"(b[0]), "r"(b[1]));
}
__device__ __forceinline__ void cp16(uint32_t smem_dst, const void* gptr) {
    asm volatile("cp.async.cg.shared.global [%0], [%1], 16;"
                 :: "r"(smem_dst), "l"(gptr));
}
__device__ __forceinline__ void cp_commit() {
    asm volatile("cp.async.commit_group;");
}
__device__ __forceinline__ void cp_wait1() {
    asm volatile("cp.async.wait_group 1;");
}
__device__ __forceinline__ void cp_wait0() {
    asm volatile("cp.async.wait_group 0;");
}

// ---------------------------------------------------------------------------
// tf32 RNA rounding pass (float4 grid-stride)
// ---------------------------------------------------------------------------
__global__ __launch_bounds__(256)
void rnd_kernel(const float* __restrict__ src, float* __restrict__ dst, int n4)
{
    int i = blockIdx.x * 256 + threadIdx.x;
    int stride = gridDim.x * 256;
    for (; i < n4; i += stride) {
        float4 v = ((const float4*)src)[i];
        v.x = to_tf32(v.x); v.y = to_tf32(v.y);
        v.z = to_tf32(v.z); v.w = to_tf32(v.w);
        ((float4*)dst)[i] = v;
    }
}

// ---------------------------------------------------------------------------
// TF32 tensor-core TN GEMM: C[M,N] = A[M,Kd]*B[N,Kd]^T + bias[N]
// Operands MUST already be tf32-rounded fp32. cp.async 3-stage pipeline,
// BK=32, tile 128x128, 8 warps (32m x 64n each), full-XOR smem swizzle.
// Optional rounded secondary output Crt. Kd multiple of 32 (>=64).
// ---------------------------------------------------------------------------
#define ST_FLOATS 4096          // 128 rows * 32 k per stage
__global__ __launch_bounds__(256, 2)
void gemm_tf32p(const float* __restrict__ A, int lda, long long Az,
                const float* __restrict__ Bm, int ldb, long long Bz,
                float* __restrict__ C, int ldcc, long long Cz,
                float* __restrict__ Crt,
                const float* __restrict__ bias, int biasz,
                int Kd)
{
    extern __shared__ __align__(128) float sm[];
    float* smA = sm;                 // 3 stages
    float* smB = sm + 3 * ST_FLOATS; // 3 stages

    A    += (long long)blockIdx.z * Az;
    Bm   += (long long)blockIdx.z * Bz;
    C    += (long long)blockIdx.z * Cz;
    bias += (long long)blockIdx.z * biasz;

    const int tid  = threadIdx.x;
    const int lane = tid & 31;
    const int w    = tid >> 5;
    const int wm   = (w & 3) * 32;
    const int wn   = (w >> 2) * 64;
    const int m0   = blockIdx.y * 128;
    const int n0   = blockIdx.x * 128;

    // cp.async mapping: thread handles chunk col c = tid&7 at rows r0+32*i
    const int r0   = tid >> 3;            // 0..31
    const int cch  = tid & 7;             // 16B chunk
    const int swc  = (cch ^ (r0 & 7)) << 4;   // swizzled byte offset of chunk
    const uint32_t sA0 = smem_u32(smA);
    const uint32_t sB0 = smem_u32(smB);
    const float* gA = A + (size_t)(m0 + r0) * lda + cch * 4;
    const float* gB = Bm + (size_t)(n0 + r0) * ldb + cch * 4;

    // ldmatrix lane mappings (same as validated R3 kernel)
    const int a_row0  = wm + (lane & 15);
    const int a_khalf = lane >> 4;
    const int b_row0  = wn + ((lane >> 4) & 1) * 8 + (lane & 7);
    const int b_half  = (lane >> 3) & 1;

    float acc[2][8][4];
#pragma unroll
    for (int mt = 0; mt < 2; mt++)
#pragma unroll
        for (int nt = 0; nt < 8; nt++)
#pragma unroll
            for (int i = 0; i < 4; i++) acc[mt][nt][i] = 0.f;

    const int nk = Kd >> 5;   // 32-deep k-tiles

    // issue loads for stage s covering k-offset ko
    auto issue = [&](int s, int ko) {
        uint32_t dA = sA0 + (uint32_t)(s * ST_FLOATS * 4) + (uint32_t)(r0 * 128) + swc;
        uint32_t dB = sB0 + (uint32_t)(s * ST_FLOATS * 4) + (uint32_t)(r0 * 128) + swc;
        const float* pA = gA + ko;
        const float* pB = gB + ko;
#pragma unroll
        for (int i = 0; i < 4; i++) {
            cp16(dA + i * 32 * 128, pA + (size_t)i * 32 * lda);
            cp16(dB + i * 32 * 128, pB + (size_t)i * 32 * ldb);
        }
    };

    issue(0, 0);  cp_commit();
    issue(1, 32); cp_commit();

    for (int kt = 0; kt < nk; kt++) {
        if (kt < nk - 1) cp_wait1(); else cp_wait0();
        __syncthreads();
        if (kt + 2 < nk) issue((kt + 2) % 3, (kt + 2) * 32);
        cp_commit();

        const int st = kt % 3;
        const uint32_t baseA = sA0 + (uint32_t)(st * ST_FLOATS * 4);
        const uint32_t baseB = sB0 + (uint32_t)(st * ST_FLOATS * 4);
#pragma unroll
        for (int ks = 0; ks < 4; ks++) {
            uint32_t af[2][4], bf[4][4];
#pragma unroll
            for (int mt = 0; mt < 2; mt++) {
                int r = a_row0 + mt * 16;
                int chunk = ks * 2 + a_khalf;
                uint32_t addr = baseA + (uint32_t)(r * 128) + (uint32_t)(((chunk ^ (r & 7)) << 4));
                ldsm4(addr, af[mt][0], af[mt][1], af[mt][2], af[mt][3]);
            }
#pragma unroll
            for (int jp = 0; jp < 4; jp++) {
                int r = b_row0 + jp * 16;
                int chunk = ks * 2 + b_half;
                uint32_t addr = baseB + (uint32_t)(r * 128) + (uint32_t)(((chunk ^ (r & 7)) << 4));
                ldsm4(addr, bf[jp][0], bf[jp][1], bf[jp][2], bf[jp][3]);
            }
#pragma unroll
            for (int mt = 0; mt < 2; mt++)
#pragma unroll
                for (int jp = 0; jp < 4; jp++) {
                    mma_tf32(acc[mt][jp * 2 + 0], af[mt], &bf[jp][0]);
                    mma_tf32(acc[mt][jp * 2 + 1], af[mt], &bf[jp][2]);
                }
        }
    }

    // epilogue
    const int crow = lane >> 2;
    const int ccol = (lane & 3) * 2;
#pragma unroll
    for (int mt = 0; mt < 2; mt++) {
        int rr = m0 + wm + mt * 16 + crow;
#pragma unroll
        for (int nt = 0; nt < 8; nt++) {
            int col = n0 + wn + nt * 8 + ccol;
            float bx = bias[col], by = bias[col + 1];
            float2 v0 = make_float2(acc[mt][nt][0] + bx, acc[mt][nt][1] + by);
            float2 v1 = make_float2(acc[mt][nt][2] + bx, acc[mt][nt][3] + by);
            *(float2*)(C + (size_t)rr * ldcc + col) = v0;
            *(float2*)(C + (size_t)(rr + 8) * ldcc + col) = v1;
            if (Crt) {
                float2 r0v = make_float2(to_tf32(v0.x), to_tf32(v0.y));
                float2 r1v = make_float2(to_tf32(v1.x), to_tf32(v1.y));
                *(float2*)(Crt + (size_t)rr * ldcc + col) = r0v;
                *(float2*)(Crt + (size_t)(rr + 8) * ldcc + col) = r1v;
            }
        }
    }
}

// ---------------------------------------------------------------------------
// GRU pointwise + per-expert LayerNorm. Writes full h_new AND rounded copy.
// ---------------------------------------------------------------------------
__global__ __launch_bounds__(256)
void gru_ln_kernel(const float* __restrict__ hp,
                   const float* __restrict__ lng, const float* __restrict__ lnb,
                   float* __restrict__ outh, float* __restrict__ outh_rt)
{
    int bk = blockIdx.x;
    int b = bk >> 3, k = bk & 7;
    const float* gir = g_gi + (size_t)b * KH3c + k * H3c;
    const float* ghr = g_gh + (size_t)b * KH3c + k * H3c;
    const float* hpr = hp + (size_t)bk * Hc;
    int tid = threadIdx.x;

    float hv[4];
    float s = 0.f, sq = 0.f;
#pragma unroll
    for (int j = 0; j < 4; j++) {
        int h = tid + j * 256;
        float ir = gir[h], iz = gir[Hc + h], inn = gir[2 * Hc + h];
        float hr = ghr[h], hz = ghr[Hc + h], hn = ghr[2 * Hc + h];
        float r = 1.f / (1.f + expf(-(ir + hr)));
        float z = 1.f / (1.f + expf(-(iz + hz)));
        float n = tanhf(inn + r * hn);
        float v = (1.f - z) * n + z * hpr[h];
        hv[j] = v; s += v; sq += v * v;
    }
    __shared__ float sa[8], sb[8];
#pragma unroll
    for (int o = 16; o; o >>= 1) {
        s  += __shfl_xor_sync(0xffffffffu, s, o);
        sq += __shfl_xor_sync(0xffffffffu, sq, o);
    }
    if ((tid & 31) == 0) { sa[tid >> 5] = s; sb[tid >> 5] = sq; }
    __syncthreads();
    float ts = 0.f, tq = 0.f;
#pragma unroll
    for (int ww = 0; ww < 8; ww++) { ts += sa[ww]; tq += sb[ww]; }
    float mean = ts * (1.f / (float)Hc);
    float var = tq * (1.f / (float)Hc) - mean * mean;
    float rstd = rsqrtf(var + 1e-5f);
#pragma unroll
    for (int j = 0; j < 4; j++) {
        int h = tid + j * 256;
        float v = (hv[j] - mean) * rstd * lng[k * Hc + h] + lnb[k * Hc + h];
        outh[(size_t)bk * Hc + h] = v;
        outh_rt[(size_t)bk * Hc + h] = to_tf32(v);
    }
}

// ---------------------------------------------------------------------------
// Attention over K=8 experts. ctx written tf32-rounded (feeds W_o GEMM only).
// ---------------------------------------------------------------------------
__global__ __launch_bounds__(256)
void attn_kernel()
{
    int b = blockIdx.x / NHc;
    int n = blockIdx.x % NHc;
    const float* qv = g_q + (size_t)b * Hc + n * HDc;
    __shared__ float sc[Kc], at[Kc];
    int wid = threadIdx.x >> 5, lane = threadIdx.x & 31;

    const float* kr = g_k + ((size_t)(b * Kc + wid)) * Hc + n * HDc;
    float s = 0.f;
#pragma unroll
    for (int d = lane; d < HDc; d += 32) s += qv[d] * kr[d];
#pragma unroll
    for (int o = 16; o; o >>= 1) s += __shfl_xor_sync(0xffffffffu, s, o);
    if (lane == 0) sc[wid] = s * (1.f / 16.f);
    __syncthreads();
    if (threadIdx.x == 0) {
        float mx = sc[0];
#pragma unroll
        for (int k2 = 1; k2 < Kc; k2++) mx = fmaxf(mx, sc[k2]);
        float den = 0.f;
#pragma unroll
        for (int k2 = 0; k2 < Kc; k2++) { at[k2] = expf(sc[k2] - mx); den += at[k2]; }
        float inv = 1.f / den;
#pragma unroll
        for (int k2 = 0; k2 < Kc; k2++) at[k2] *= inv;
    }
    __syncthreads();
    int d = threadIdx.x;
    float c = 0.f;
#pragma unroll
    for (int k2 = 0; k2 < Kc; k2++)
        c += at[k2] * g_v[((size_t)(b * Kc + k2)) * Hc + n * HDc + d];
    g_ctx[(size_t)b * Hc + n * HDc + d] = to_tf32(c);
}

// ---------------------------------------------------------------------------
// context = LayerNorm(query + attn_out). One block per b.
// ---------------------------------------------------------------------------
__global__ __launch_bounds__(256)
void ln_res_kernel(const float* __restrict__ g, const float* __restrict__ bb)
{
    int b = blockIdx.x;
    const float* qr = g_query + (size_t)b * Hc;
    const float* ar = g_attno + (size_t)b * Hc;
    int tid = threadIdx.x;
    float hv[4]; float s = 0.f, sq = 0.f;
#pragma unroll
    for (int j = 0; j < 4; j++) {
        int h = tid + j * 256;
        float v = qr[h] + ar[h];
        hv[j] = v; s += v; sq += v * v;
    }
    __shared__ float sa[8], sb[8];
#pragma unroll
    for (int o = 16; o; o >>= 1) {
        s  += __shfl_xor_sync(0xffffffffu, s, o);
        sq += __shfl_xor_sync(0xffffffffu, sq, o);
    }
    if ((tid & 31) == 0) { sa[tid >> 5] = s; sb[tid >> 5] = sq; }
    __syncthreads();
    float ts = 0.f, tq = 0.f;
#pragma unroll
    for (int ww = 0; ww < 8; ww++) { ts += sa[ww]; tq += sb[ww]; }
    float mean = ts * (1.f / (float)Hc);
    float var = tq * (1.f / (float)Hc) - mean * mean;
    float rstd = rsqrtf(var + 1e-5f);
#pragma unroll
    for (int j = 0; j < 4; j++) {
        int h = tid + j * 256;
        g_context[(size_t)b * Hc + h] = (hv[j] - mean) * rstd * g[h] + bb[h];
    }
}

// ---------------------------------------------------------------------------
// Gate logits + softmax + expert mixing. mixed written tf32-rounded.
// ---------------------------------------------------------------------------
__global__ __launch_bounds__(256)
void gate_kernel(const float* __restrict__ Wg, const float* __restrict__ bg,
                 const float* __restrict__ h_new,
                 float* __restrict__ out_g, float* __restrict__ out_l)
{
    int b = blockIdx.x;
    int tid = threadIdx.x;
    int wid = tid >> 5, lane = tid & 31;
    __shared__ float lg[Kc], gt[Kc];

    const float* cr = g_context + (size_t)b * Hc;
    float s = 0.f;
#pragma unroll
    for (int h = lane; h < Hc; h += 32) s += cr[h] * Wg[wid * Hc + h];
#pragma unroll
    for (int o = 16; o; o >>= 1) s += __shfl_xor_sync(0xffffffffu, s, o);
    if (lane == 0) lg[wid] = s + bg[wid];
    __syncthreads();
    if (tid == 0) {
        float mx = lg[0];
#pragma unroll
        for (int k2 = 1; k2 < Kc; k2++) mx = fmaxf(mx, lg[k2]);
        float den = 0.f;
#pragma unroll
        for (int k2 = 0; k2 < Kc; k2++) { gt[k2] = expf(lg[k2] - mx); den += gt[k2]; }
        float inv = 1.f / den;
#pragma unroll
        for (int k2 = 0; k2 < Kc; k2++) gt[k2] *= inv;
    }
    __syncthreads();
#pragma unroll
    for (int j = 0; j < 4; j++) {
        int h = tid + j * 256;
        float m = 0.f;
#pragma unroll
        for (int k2 = 0; k2 < Kc; k2++)
            m += gt[k2] * h_new[((size_t)(b * Kc + k2)) * Hc + h];
        g_mixed[(size_t)b * Hc + h] = to_tf32(m);
    }
    if (tid < Kc) { out_l[b * Kc + tid] = lg[tid]; out_g[b * Kc + tid] = gt[tid]; }
}

// ---------------------------------------------------------------------------
extern "C" void kernel_launch(void* const* d_in, const int* in_sizes, int n_in,
                              void* d_out, int out_size)
{
    const float* x_t    = (const float*)d_in[0];
    const float* h_prev = (const float*)d_in[1];
    const float* W_ih   = (const float*)d_in[2];
    const float* W_hh   = (const float*)d_in[3];
    const float* b_ih   = (const float*)d_in[4];
    const float* b_hh   = (const float*)d_in[5];
    const float* ln_g   = (const float*)d_in[6];
    const float* ln_b   = (const float*)d_in[7];
    const float* Wqp    = (const float*)d_in[8];
    const float* bqp    = (const float*)d_in[9];
    const float* W_q    = (const float*)d_in[10];
    const float* W_k    = (const float*)d_in[11];
    const float* W_v    = (const float*)d_in[12];
    const float* b_q    = (const float*)d_in[13];
    const float* b_k    = (const float*)d_in[14];
    const float* b_v    = (const float*)d_in[15];
    const float* W_o    = (const float*)d_in[16];
    const float* b_o    = (const float*)d_in[17];
    const float* aln_g  = (const float*)d_in[18];
    const float* aln_b  = (const float*)d_in[19];
    const float* W_gate = (const float*)d_in[20];
    const float* b_gate = (const float*)d_in[21];
    const float* W_read = (const float*)d_in[22];
    const float* b_read = (const float*)d_in[23];

    float* out   = (float*)d_out;
    float* out_h = out;
    float* out_y = out_h + (size_t)Bc * Kc * Hc;
    float* out_g = out_y + (size_t)Bc * Oc;
    float* out_l = out_g + (size_t)Bc * Kc;

    float *pgi, *pgh, *pquery, *pquery_rt, *pq, *pk, *pv, *pctx, *pattno, *pmixed, *phnew_rt;
    float *px_rt, *phprev_rt, *pWih, *pWhh, *pWqp, *pWq, *pWk, *pWv, *pWo, *pWread;
    cudaGetSymbolAddress((void**)&pgi,       g_gi);
    cudaGetSymbolAddress((void**)&pgh,       g_gh);
    cudaGetSymbolAddress((void**)&pquery,    g_query);
    cudaGetSymbolAddress((void**)&pquery_rt, g_query_rt);
    cudaGetSymbolAddress((void**)&pq,        g_q);
    cudaGetSymbolAddress((void**)&pk,        g_k);
    cudaGetSymbolAddress((void**)&pv,        g_v);
    cudaGetSymbolAddress((void**)&pctx,      g_ctx);
    cudaGetSymbolAddress((void**)&pattno,    g_attno);
    cudaGetSymbolAddress((void**)&pmixed,    g_mixed);
    cudaGetSymbolAddress((void**)&phnew_rt,  g_hnew_rt);
    cudaGetSymbolAddress((void**)&px_rt,     g_x_rt);
    cudaGetSymbolAddress((void**)&phprev_rt, g_hprev_rt);
    cudaGetSymbolAddress((void**)&pWih,      g_Wih_rt);
    cudaGetSymbolAddress((void**)&pWhh,      g_Whh_rt);
    cudaGetSymbolAddress((void**)&pWqp,      g_Wqp_rt);
    cudaGetSymbolAddress((void**)&pWq,       g_Wq_rt);
    cudaGetSymbolAddress((void**)&pWk,       g_Wk_rt);
    cudaGetSymbolAddress((void**)&pWv,       g_Wv_rt);
    cudaGetSymbolAddress((void**)&pWo,       g_Wo_rt);
    cudaGetSymbolAddress((void**)&pWread,    g_Wread_rt);

    static bool attr_set = false;
    if (!attr_set) {
        cudaFuncSetAttribute(gemm_tf32p,
            cudaFuncAttributeMaxDynamicSharedMemorySize, 6 * ST_FLOATS * 4);
        attr_set = true;
    }
    const int SMEM = 6 * ST_FLOATS * 4;   // 96 KB

    dim3 blk(256);
    // --- pre-round static GEMM operands to tf32 ---
    rnd_kernel<<<512, blk>>>(x_t,    px_rt,     Bc * Dc / 4);
    rnd_kernel<<<2048, blk>>>(h_prev, phprev_rt, Bc * Kc * Hc / 4);
    rnd_kernel<<<2048, blk>>>(W_ih,   pWih,      KH3c * Dc / 4);
    rnd_kernel<<<2048, blk>>>(W_hh,   pWhh,      Kc * H3c * Hc / 4);
    rnd_kernel<<<256, blk>>>(Wqp,    pWqp,      Hc * Dc / 4);
    rnd_kernel<<<512, blk>>>(W_q,    pWq,       Hc * Hc / 4);
    rnd_kernel<<<512, blk>>>(W_k,    pWk,       Hc * Hc / 4);
    rnd_kernel<<<512, blk>>>(W_v,    pWv,       Hc * Hc / 4);
    rnd_kernel<<<512, blk>>>(W_o,    pWo,       Hc * Hc / 4);
    rnd_kernel<<<128, blk>>>(W_read, pWread,    Oc * Hc / 4);

    // gi = x @ W_ih^T + b_ih
    gemm_tf32p<<<dim3(KH3c / 128, Bc / 128, 1), blk, SMEM>>>(
        px_rt, Dc, 0, pWih, Dc, 0, pgi, KH3c, 0, nullptr, b_ih, 0, Dc);

    // gh[k] = h_prev[:,k,:] @ W_hh[k]^T + b_hh[k]
    gemm_tf32p<<<dim3(H3c / 128, Bc / 128, Kc), blk, SMEM>>>(
        phprev_rt, Kc * Hc, (long long)Hc,
        pWhh, Hc, (long long)H3c * Hc,
        pgh, KH3c, (long long)H3c,
        nullptr, b_hh, H3c, Hc);

    // query = x @ Wqp^T + bqp  (+ rounded copy for q GEMM)
    gemm_tf32p<<<dim3(Hc / 128, Bc / 128, 1), blk, SMEM>>>(
        px_rt, Dc, 0, pWqp, Dc, 0, pquery, Hc, 0, pquery_rt, bqp, 0, Dc);

    // GRU pointwise + per-expert LN -> h_new (full to out, rounded to scratch)
    gru_ln_kernel<<<Bc * Kc, blk>>>(h_prev, ln_g, ln_b, out_h, phnew_rt);

    // q = query @ W_q^T + b_q
    gemm_tf32p<<<dim3(Hc / 128, Bc / 128, 1), blk, SMEM>>>(
        pquery_rt, Hc, 0, pWq, Hc, 0, pq, Hc, 0, nullptr, b_q, 0, Hc);

    // k = h_new @ W_k^T + b_k
    gemm_tf32p<<<dim3(Hc / 128, (Bc * Kc) / 128, 1), blk, SMEM>>>(
        phnew_rt, Hc, 0, pWk, Hc, 0, pk, Hc, 0, nullptr, b_k, 0, Hc);

    // v = h_new @ W_v^T + b_v
    gemm_tf32p<<<dim3(Hc / 128, (Bc * Kc) / 128, 1), blk, SMEM>>>(
        phnew_rt, Hc, 0, pWv, Hc, 0, pv, Hc, 0, nullptr, b_v, 0, Hc);

    // attention over experts -> ctx (rounded at write)
    attn_kernel<<<Bc * NHc, blk>>>();

    // attn_out = ctx @ W_o^T + b_o
    gemm_tf32p<<<dim3(Hc / 128, Bc / 128, 1), blk, SMEM>>>(
        pctx, Hc, 0, pWo, Hc, 0, pattno, Hc, 0, nullptr, b_o, 0, Hc);

    // context = LN(query + attn_out)
    ln_res_kernel<<<Bc, blk>>>(aln_g, aln_b);

    // logits/g_t/mixed_h (mixed rounded at write)
    gate_kernel<<<Bc, blk>>>(W_gate, b_gate, out_h, out_g, out_l);

    // y_hat = mixed @ W_read^T + b_read
    gemm_tf32p<<<dim3(Oc / 128, Bc / 128, 1), blk, SMEM>>>(
        pmixed, Hc, 0, pWread, Hc, 0, out_y, Oc, 0, nullptr, b_read, 0, Hc);
}